// round 1
// baseline (speedup 1.0000x reference)
#include <cuda_runtime.h>

// VINeuralODE: B=128 samples, D=32, H=128, 8 Dopri5 steps (6 field evals each).
// Key identity: dlogpdt = -tr(W3 D2 W2 D1 W1) = -d1^T M d2,
//   M[k,j] = (W1@W3)[k,j] * W2[j,k]  (input independent -> precomputed once).
// One block per sample, 256 threads; weights register-resident per thread.

#define Dd 32
#define Hh 128
#define NSTEPS 8

__device__ __align__(16) float d_M[Hh * Hh];

__constant__ float c_C[6] = {0.0f, 0.2f, 0.3f, 0.8f, 0.88888888888888888f, 1.0f};

__global__ void precompute_M_kernel(const float* __restrict__ W1,
                                    const float* __restrict__ W2,
                                    const float* __restrict__ W3) {
    int jj = blockIdx.x;   // column of M
    int kk = threadIdx.x;  // row of M
    float a = 0.f;
#pragma unroll
    for (int i = 0; i < Dd; ++i)
        a += W1[kk * Dd + i] * W3[i * Hh + jj];
    d_M[kk * Hh + jj] = a * W2[jj * Hh + kk];
}

__global__ __launch_bounds__(256, 1)
void ode_kernel(const float* __restrict__ x0,
                const float* __restrict__ W1,
                const float* __restrict__ u1,
                const float* __restrict__ b1,
                const float* __restrict__ W2,
                const float* __restrict__ b2,
                const float* __restrict__ W3,
                const float* __restrict__ b3,
                const float* __restrict__ prec,
                float* __restrict__ out, int B) {
    const int s   = blockIdx.x;
    const int tid = threadIdx.x;
    const int j   = tid & (Hh - 1);  // row owned (0..127)
    const int h   = tid >> 7;        // half (0/1)
    const int r   = tid & 31;        // lane
    const int seg = tid >> 5;        // 0..7
    const float dt = 1.0f / NSTEPS;
    const float HALF_LOG2PI = 0.9189385332046727f;

    __shared__ __align__(16) float sh_xs[Dd];
    __shared__ __align__(16) float sh_h1[Hh];
    __shared__ __align__(16) float sh_h2[Hh];
    __shared__ __align__(16) float sh_d2[Hh];
    __shared__ float sh_p1[256];
    __shared__ float sh_mp[256];
    __shared__ float sh_dxp[256];
    __shared__ float sh_p[Hh];
    __shared__ float sh_k[6][34];
    __shared__ float sh_y[34];
    __shared__ float b1s[Hh], u1s[Hh], b2s[Hh], b3s[Dd], precs[Dd];

    // ---- register-resident weights ----
    float w1r[Dd];    // W1 row j (full)
    float w2r[64];    // W2 row j, half h
    float wmr[64];    // M  row j, half h
    float w3r[16];    // W3 row r, segment seg (16 cols)
    {
        const float4* p = (const float4*)(W1 + j * Dd);
#pragma unroll
        for (int i = 0; i < 8; ++i) {
            float4 v = p[i];
            w1r[4*i] = v.x; w1r[4*i+1] = v.y; w1r[4*i+2] = v.z; w1r[4*i+3] = v.w;
        }
    }
    {
        const float4* p = (const float4*)(W2 + j * Hh + h * 64);
#pragma unroll
        for (int i = 0; i < 16; ++i) {
            float4 v = p[i];
            w2r[4*i] = v.x; w2r[4*i+1] = v.y; w2r[4*i+2] = v.z; w2r[4*i+3] = v.w;
        }
    }
    {
        const float4* p = (const float4*)(d_M + j * Hh + h * 64);
#pragma unroll
        for (int i = 0; i < 16; ++i) {
            float4 v = p[i];
            wmr[4*i] = v.x; wmr[4*i+1] = v.y; wmr[4*i+2] = v.z; wmr[4*i+3] = v.w;
        }
    }
    {
        const float4* p = (const float4*)(W3 + r * Hh + seg * 16);
#pragma unroll
        for (int i = 0; i < 4; ++i) {
            float4 v = p[i];
            w3r[4*i] = v.x; w3r[4*i+1] = v.y; w3r[4*i+2] = v.z; w3r[4*i+3] = v.w;
        }
    }
    if (tid < Hh) { b1s[tid] = b1[tid]; u1s[tid] = u1[tid]; b2s[tid] = b2[tid]; }
    if (tid < Dd) { b3s[tid] = b3[tid]; precs[tid] = prec[tid]; }
    if (tid < 34) {
        float yv = (tid < Dd) ? x0[s * Dd + tid] : 0.f;
        sh_y[tid] = yv;
        if (tid < Dd) sh_xs[tid] = yv;
    }
    __syncthreads();

    float d1v = 0.f;  // (1 - h1^2) for row tid, valid for tid < 128

    for (int step = 0; step < NSTEPS; ++step) {
        float t0 = (float)step * dt;
#pragma unroll 1
        for (int st = 0; st < 6; ++st) {
            float ts = t0 + c_C[st] * dt;

            // ---- phase 1: h1 (every thread computes its full row j) ----
            {
                float a = b1s[j] + ts * u1s[j];
#pragma unroll
                for (int i = 0; i < Dd; i += 4) {
                    float4 xv = *(const float4*)(sh_xs + i);
                    a += w1r[i] * xv.x + w1r[i+1] * xv.y + w1r[i+2] * xv.z + w1r[i+3] * xv.w;
                }
                float h1 = tanhf(a);
                if (tid < Hh) { sh_h1[tid] = h1; d1v = 1.f - h1 * h1; }
            }
            __syncthreads();

            // ---- phase 2: h2 half-row partials ----
            {
                float acc = 0.f;
#pragma unroll
                for (int i = 0; i < 64; i += 4) {
                    float4 hv = *(const float4*)(sh_h1 + h * 64 + i);
                    acc += w2r[i] * hv.x + w2r[i+1] * hv.y + w2r[i+2] * hv.z + w2r[i+3] * hv.w;
                }
                sh_p1[tid] = acc;
            }
            __syncthreads();

            // ---- phase 3: h2 combine ----
            if (tid < Hh) {
                float b = sh_p1[tid] + sh_p1[tid + 128] + b2s[tid];
                float h2 = tanhf(b);
                sh_h2[tid] = h2;
                sh_d2[tid] = 1.f - h2 * h2;
            }
            __syncthreads();

            // ---- phase 4: M@d2 half-row partials + W3@h2 segment partials ----
            {
                float acc = 0.f;
#pragma unroll
                for (int i = 0; i < 64; i += 4) {
                    float4 dv = *(const float4*)(sh_d2 + h * 64 + i);
                    acc += wmr[i] * dv.x + wmr[i+1] * dv.y + wmr[i+2] * dv.z + wmr[i+3] * dv.w;
                }
                sh_mp[tid] = acc;
                float accd = 0.f;
#pragma unroll
                for (int i = 0; i < 16; i += 4) {
                    float4 hv = *(const float4*)(sh_h2 + seg * 16 + i);
                    accd += w3r[i] * hv.x + w3r[i+1] * hv.y + w3r[i+2] * hv.z + w3r[i+3] * hv.w;
                }
                sh_dxp[tid] = accd;
            }
            __syncthreads();

            // ---- phase 5: p_k = d1_k * (M d2)_k ; dxdt rows ----
            float dxv = 0.f;
            if (tid < Hh) sh_p[tid] = d1v * (sh_mp[tid] + sh_mp[tid + 128]);
            if (tid < 32) {
                dxv = b3s[r];
#pragma unroll
                for (int sg = 0; sg < 8; ++sg) dxv += sh_dxp[sg * 32 + r];
                sh_k[st][r] = dxv;
            }
            __syncthreads();

            // ---- phase 6 (warp 0): trace + dkldt reductions, next stage xs ----
            if (tid < 32) {
                float p4 = sh_p[r] + sh_p[r + 32] + sh_p[r + 64] + sh_p[r + 96];
                float xv = sh_xs[r];
                float omt = 1.f - ts;
                float cA = -0.5f * omt * omt;
                float cB = -0.5f * omt * (1.f + ts);
                float q = (cA * (-0.5f * xv * xv - HALF_LOG2PI) + cB * (-precs[r] * xv)) * dxv;
#pragma unroll
                for (int off = 16; off > 0; off >>= 1) {
                    p4 += __shfl_xor_sync(0xffffffffu, p4, off);
                    q  += __shfl_xor_sync(0xffffffffu, q, off);
                }
                if (r == 0) {
                    sh_k[st][32] = -p4;                 // dlogpdt
                    sh_k[st][33] = q + omt * (-p4);     // dkldt
                }
                if (st < 5) {
                    float acc;
                    switch (st) {
                        case 0: acc = 0.2f * sh_k[0][r]; break;
                        case 1: acc = (3.f/40.f) * sh_k[0][r] + (9.f/40.f) * sh_k[1][r]; break;
                        case 2: acc = (44.f/45.f) * sh_k[0][r] + (-56.f/15.f) * sh_k[1][r]
                                    + (32.f/9.f) * sh_k[2][r]; break;
                        case 3: acc = (19372.f/6561.f) * sh_k[0][r] + (-25360.f/2187.f) * sh_k[1][r]
                                    + (64448.f/6561.f) * sh_k[2][r] + (-212.f/729.f) * sh_k[3][r]; break;
                        default: acc = (9017.f/3168.f) * sh_k[0][r] + (-355.f/33.f) * sh_k[1][r]
                                     + (46732.f/5247.f) * sh_k[2][r] + (49.f/176.f) * sh_k[3][r]
                                     + (-5103.f/18656.f) * sh_k[4][r]; break;
                    }
                    sh_xs[r] = sh_y[r] + dt * acc;
                }
            }
            __syncthreads();
        }

        // ---- y update (dopri5 5th-order combination) ----
        if (tid < 34) {
            float acc = sh_y[tid] + dt * ( (35.f/384.f)    * sh_k[0][tid]
                                         + (500.f/1113.f)  * sh_k[2][tid]
                                         + (125.f/192.f)   * sh_k[3][tid]
                                         + (-2187.f/6784.f)* sh_k[4][tid]
                                         + (11.f/84.f)     * sh_k[5][tid] );
            sh_y[tid] = acc;
            if (tid < Dd) sh_xs[tid] = acc;
        }
        __syncthreads();
    }

    // ---- outputs: z, log_px0 + log_det, kl ----
    if (tid < Dd) out[s * Dd + tid] = sh_y[tid];
    if (tid < 32) {
        float xv = x0[s * Dd + r];
        float lp = -0.5f * xv * xv - HALF_LOG2PI;
#pragma unroll
        for (int off = 16; off > 0; off >>= 1)
            lp += __shfl_xor_sync(0xffffffffu, lp, off);
        if (r == 0) {
            out[B * Dd + s]     = lp + sh_y[32];
            out[B * Dd + B + s] = sh_y[33];
        }
    }
}

extern "C" void kernel_launch(void* const* d_in, const int* in_sizes, int n_in,
                              void* d_out, int out_size) {
    const float* x0   = (const float*)d_in[0];
    const float* W1   = (const float*)d_in[1];
    const float* u1   = (const float*)d_in[2];
    const float* b1   = (const float*)d_in[3];
    const float* W2   = (const float*)d_in[4];
    const float* b2   = (const float*)d_in[5];
    const float* W3   = (const float*)d_in[6];
    const float* b3   = (const float*)d_in[7];
    const float* prec = (const float*)d_in[8];
    float* out = (float*)d_out;
    const int B = in_sizes[0] / Dd;

    precompute_M_kernel<<<Hh, Hh>>>(W1, W2, W3);
    ode_kernel<<<B, 256>>>(x0, W1, u1, b1, W2, b2, W3, b3, prec, out, B);
}